// round 4
// baseline (speedup 1.0000x reference)
#include <cuda_runtime.h>
#include <cuda_bf16.h>
#include <cstdint>
#include <math.h>

// Problem constants
#define T_STEPS 256
#define BATCH   25
#define VOCAB   32000
#define HID     1024
#define CLS     2
#define M_GEMM  (T_STEPS * BATCH)   // 6400

// ---------------- scratch (device globals: no allocation allowed) -------------
__device__ __align__(16) float g_Z[M_GEMM * HID];        // 26.2 MB: X @ W_xh
__device__ __align__(16) float g_h[2][BATCH * HID];      // double-buffered state
__device__ unsigned g_bar_cnt = 0;
__device__ volatile unsigned g_bar_gen = 0;

// ============================ helpers =========================================
__device__ __forceinline__ uint32_t smem_u32(const void* p) {
    uint32_t a;
    asm("{ .reg .u64 t; cvta.to.shared.u64 t, %1; cvt.u32.u64 %0, t; }" : "=r"(a) : "l"(p));
    return a;
}
__device__ __forceinline__ void cp_async16(uint32_t saddr, const void* g) {
    asm volatile("cp.async.cg.shared.global [%0], [%1], 16;\n" :: "r"(saddr), "l"(g));
}
__device__ __forceinline__ void cp_commit() {
    asm volatile("cp.async.commit_group;\n" ::: "memory");
}
__device__ __forceinline__ void cp_wait2() {
    asm volatile("cp.async.wait_group 2;\n" ::: "memory");
}
__device__ __forceinline__ void mma_tf32(float* d, const float* a, const float* b) {
    asm volatile(
        "mma.sync.aligned.m16n8k8.row.col.f32.tf32.tf32.f32 "
        "{%0,%1,%2,%3}, {%4,%5,%6,%7}, {%8,%9}, {%0,%1,%2,%3};\n"
        : "+f"(d[0]), "+f"(d[1]), "+f"(d[2]), "+f"(d[3])
        : "r"(__float_as_uint(a[0])), "r"(__float_as_uint(a[1])),
          "r"(__float_as_uint(a[2])), "r"(__float_as_uint(a[3])),
          "r"(__float_as_uint(b[0])), "r"(__float_as_uint(b[1])));
}

// ============== Kernel 1: Z = X @ W_xh via mma.sync tf32 ======================
// BM=128, BN=128, BK=16. 8 warps as 2(m) x 4(n), warp tile 64x32.
// 4-stage cp.async pipeline, 2 CTAs/SM (16 warps/SM for latency hiding).
#define BM 128
#define BN 128
#define BK 16
#define STAGES 4
#define NITER (VOCAB / BK)           // 2000

#define A_PAD 20                     // floats per A row  (bank: 20g+t distinct)
#define B_PAD 136                    // floats per B row  (bank: 8t+g distinct)
#define A_FLOATS (BM * A_PAD)        // 2560  (10 KB)
#define B_FLOATS (BK * B_PAD)        // 2176  (8.5 KB)
#define STAGE_FLOATS (A_FLOATS + B_FLOATS)
#define GEMM_DYNSMEM (STAGES * STAGE_FLOATS * 4)   // ~74 KB

extern __shared__ float smem[];

__global__ __launch_bounds__(256, 2) void gemm_tc_kernel(
    const float* __restrict__ A,   // X    [6400, 32000] row-major (K contig)
    const float* __restrict__ B,   // W_xh [32000, 1024] row-major (N contig)
    float* __restrict__ C)         // Z    [6400, 1024]
{
    const int tid  = threadIdx.x;
    const int wid  = tid >> 5;
    const int lane = tid & 31;
    const int g    = lane >> 2;     // group id 0..7
    const int t    = lane & 3;      // thread-in-group 0..3
    const int wm   = wid >> 2;      // 0..1   (64-row slab)
    const int wn   = wid & 3;       // 0..3   (32-col slab)
    const int m0   = blockIdx.y * BM;
    const int n0   = blockIdx.x * BN;

    const uint32_t sbase = smem_u32(smem);

    auto load_stage = [&](int it) {
        const int s = it & 3;
        const uint32_t abase = sbase + s * STAGE_FLOATS * 4;
        const uint32_t bbase = abase + A_FLOATS * 4;
        const float* Ag = A + (size_t)m0 * VOCAB + (size_t)it * BK;
        const float* Bg = B + (size_t)it * BK * HID + n0;
#pragma unroll
        for (int i = 0; i < 2; i++) {        // A: 512 granules of 16B
            int q = tid + i * 256;
            int r = q >> 2, c = q & 3;
            cp_async16(abase + (r * A_PAD + c * 4) * 4,
                       Ag + (size_t)r * VOCAB + c * 4);
        }
#pragma unroll
        for (int i = 0; i < 2; i++) {        // B: 512 granules of 16B
            int q = tid + i * 256;
            int r = q >> 5, c = q & 31;
            cp_async16(bbase + (r * B_PAD + c * 4) * 4,
                       Bg + (size_t)r * HID + c * 4);
        }
        cp_commit();
    };

    float acc[4][4][4];
#pragma unroll
    for (int i = 0; i < 4; i++)
#pragma unroll
        for (int j = 0; j < 4; j++)
#pragma unroll
            for (int k = 0; k < 4; k++) acc[i][j][k] = 0.0f;

    // prologue: 3 stages in flight
    load_stage(0); load_stage(1); load_stage(2);

#pragma unroll 1
    for (int it = 0; it < NITER; it++) {
        cp_wait2();
        __syncthreads();
        const int s = it & 3;
        const float* As = smem + s * STAGE_FLOATS;            // [128][20]
        const float* Bs = As + A_FLOATS;                      // [16][136]

#pragma unroll
        for (int k8 = 0; k8 < BK / 8; k8++) {
            float af[4][4];
#pragma unroll
            for (int mt = 0; mt < 4; mt++) {
                const int mrow = wm * 64 + mt * 16 + g;
                const float* ap = As + mrow * A_PAD + k8 * 8;
                af[mt][0] = ap[t];
                af[mt][1] = ap[8 * A_PAD + t];
                af[mt][2] = ap[t + 4];
                af[mt][3] = ap[8 * A_PAD + t + 4];
            }
            float bf[4][2];
#pragma unroll
            for (int nt = 0; nt < 4; nt++) {
                const int ncol = wn * 32 + nt * 8 + g;
                const float* bp = Bs + (k8 * 8 + t) * B_PAD + ncol;
                bf[nt][0] = bp[0];
                bf[nt][1] = bp[4 * B_PAD];
            }
#pragma unroll
            for (int mt = 0; mt < 4; mt++)
#pragma unroll
                for (int nt = 0; nt < 4; nt++)
                    mma_tf32(acc[mt][nt], af[mt], bf[nt]);
        }

        if (it + 3 < NITER) load_stage(it + 3);
    }

    // epilogue: direct register -> global stores (float2)
#pragma unroll
    for (int mt = 0; mt < 4; mt++) {
#pragma unroll
        for (int nt = 0; nt < 4; nt++) {
            const int r0 = m0 + wm * 64 + mt * 16 + g;
            const int c  = n0 + wn * 32 + nt * 8 + 2 * t;
            float2 v0 = make_float2(acc[mt][nt][0], acc[mt][nt][1]);
            float2 v1 = make_float2(acc[mt][nt][2], acc[mt][nt][3]);
            *reinterpret_cast<float2*>(C + (size_t)r0 * HID + c) = v0;
            *reinterpret_cast<float2*>(C + (size_t)(r0 + 8) * HID + c) = v1;
        }
    }
}

// ============ profiler-alignment dummy (steers ncu -s5 onto gemm) =============
__global__ void dummy_kernel() {}

// ================= Kernel 2: recurrence + pool + fc + softmax =================
#define NB 128
#define CPB 8

__device__ __forceinline__ void gridbar() {
    __syncthreads();
    if (threadIdx.x == 0) {
        unsigned gen = g_bar_gen;
        __threadfence();
        if (atomicAdd(&g_bar_cnt, 1) == NB - 1) {
            atomicExch(&g_bar_cnt, 0);
            __threadfence();
            g_bar_gen = gen + 1;
        } else {
            while (g_bar_gen == gen) { __nanosleep(64); }
            __threadfence();
        }
    }
    __syncthreads();
}

__global__ __launch_bounds__(256, 1) void rnn_recurrence_kernel(
    const float* __restrict__ W_hh,   // [1024, 1024] (k, n)
    const float* __restrict__ b_h,    // [1024]
    const float* __restrict__ fc_w,   // [1024, 2]
    const float* __restrict__ fc_b,   // [2]
    float* __restrict__ out)          // [2]
{
    __shared__ float Ws[CPB][HID];
    const int tid = threadIdx.x;
    const int wid = tid >> 5;
    const int lane = tid & 31;
    const int c0 = blockIdx.x * CPB;

    for (int i = tid; i < CPB * HID; i += 256) {
        int c = i >> 10, k = i & (HID - 1);
        Ws[c][k] = W_hh[k * HID + c0 + c];
    }
    for (int i = tid; i < 200; i += 256)
        g_h[0][blockIdx.x * 200 + i] = 0.0f;
    gridbar();

    const float4* Ws4 = reinterpret_cast<const float4*>(&Ws[0][0]);

    for (int t = 0; t < T_STEPS; t++) {
        const int rb = t & 1, wb = rb ^ 1;
        const float4* h4 = reinterpret_cast<const float4*>(g_h[rb]);
        for (int b = wid; b < BATCH; b += 8) {
            float acc[CPB];
#pragma unroll
            for (int c = 0; c < CPB; c++) acc[c] = 0.0f;
            const float4* hrow = h4 + b * (HID / 4);
#pragma unroll
            for (int p = 0; p < 8; p++) {
                float4 hv = __ldcg(&hrow[p * 32 + lane]);
#pragma unroll
                for (int c = 0; c < CPB; c++) {
                    float4 wv = Ws4[c * 256 + p * 32 + lane];
                    acc[c] += hv.x * wv.x + hv.y * wv.y + hv.z * wv.z + hv.w * wv.w;
                }
            }
#pragma unroll
            for (int c = 0; c < CPB; c++) {
#pragma unroll
                for (int off = 16; off; off >>= 1)
                    acc[c] += __shfl_xor_sync(0xFFFFFFFFu, acc[c], off);
            }
            if (lane == 0) {
                const float* zrow = g_Z + ((size_t)t * BATCH + b) * HID + c0;
                float* hn = g_h[wb] + b * HID + c0;
#pragma unroll
                for (int c = 0; c < CPB; c++)
                    hn[c] = tanhf(zrow[c] + b_h[c0 + c] + acc[c]);
            }
        }
        gridbar();
    }

    if (blockIdx.x == 0) {
        __shared__ float red0[8], red1[8];
        float l0 = 0.0f, l1 = 0.0f;
        for (int n = tid; n < HID; n += 256) {
            float s = 0.0f;
#pragma unroll
            for (int b = 0; b < BATCH; b++)
                s += __ldcg(&g_h[0][b * HID + n]);
            float pooled = s * (1.0f / BATCH);
            l0 += pooled * fc_w[n * CLS + 0];
            l1 += pooled * fc_w[n * CLS + 1];
        }
#pragma unroll
        for (int off = 16; off; off >>= 1) {
            l0 += __shfl_xor_sync(0xFFFFFFFFu, l0, off);
            l1 += __shfl_xor_sync(0xFFFFFFFFu, l1, off);
        }
        if (lane == 0) { red0[wid] = l0; red1[wid] = l1; }
        __syncthreads();
        if (tid == 0) {
            float a = 0.0f, c = 0.0f;
#pragma unroll
            for (int w = 0; w < 8; w++) { a += red0[w]; c += red1[w]; }
            a += fc_b[0]; c += fc_b[1];
            float mx = fmaxf(a, c);
            float e0 = expf(a - mx), e1 = expf(c - mx);
            float inv = 1.0f / (e0 + e1);
            out[0] = e0 * inv;
            out[1] = e1 * inv;
        }
    }
}

// ================================ launcher ====================================
extern "C" void kernel_launch(void* const* d_in, const int* in_sizes, int n_in,
                              void* d_out, int out_size) {
    const float* X    = (const float*)d_in[0];
    const float* W_xh = (const float*)d_in[1];
    const float* W_hh = (const float*)d_in[2];
    const float* b_h  = (const float*)d_in[3];
    const float* fc_w = (const float*)d_in[4];
    const float* fc_b = (const float*)d_in[5];
    float* out = (float*)d_out;

    float* Z;
    cudaGetSymbolAddress((void**)&Z, g_Z);

    cudaFuncSetAttribute(gemm_tc_kernel,
                         cudaFuncAttributeMaxDynamicSharedMemorySize, GEMM_DYNSMEM);

    // Launch sequence (d, g, d, r): with ncu -s 5 -c 1 the 6th launch across
    // replays is the GEMM, so the profile finally shows the hot kernel.
    dummy_kernel<<<1, 32>>>();
    dim3 ggrid(HID / BN, M_GEMM / BM);         // (8, 50)
    gemm_tc_kernel<<<ggrid, 256, GEMM_DYNSMEM>>>(X, W_xh, Z);
    dummy_kernel<<<1, 32>>>();
    rnn_recurrence_kernel<<<NB, 256>>>(W_hh, b_h, fc_w, fc_b, out);
}

// round 5
// speedup vs baseline: 1.3966x; 1.3966x over previous
#include <cuda_runtime.h>
#include <cuda_fp16.h>
#include <cstdint>
#include <math.h>

// Problem constants
#define T_STEPS 256
#define BATCH   25
#define VOCAB   32000
#define HID     1024
#define CLS     2
#define M_GEMM  (T_STEPS * BATCH)   // 6400

// ---------------- scratch (device globals: no allocation allowed) -------------
__device__ __align__(16) float  g_Z[M_GEMM * HID];        // 26.2 MB
__device__ __align__(16) __half g_Xh[(size_t)M_GEMM * VOCAB];  // 410 MB fp16 X
__device__ __align__(16) __half g_Wh[(size_t)VOCAB * HID];     // 65.5 MB fp16 W_xh
__device__ __align__(16) float  g_h[2][BATCH * HID];
__device__ unsigned g_bar_cnt = 0;
__device__ volatile unsigned g_bar_gen = 0;

// ============================ helpers =========================================
__device__ __forceinline__ uint32_t smem_u32(const void* p) {
    uint32_t a;
    asm("{ .reg .u64 t; cvta.to.shared.u64 t, %1; cvt.u32.u64 %0, t; }" : "=r"(a) : "l"(p));
    return a;
}
__device__ __forceinline__ void cp_async16(uint32_t saddr, const void* g) {
    asm volatile("cp.async.cg.shared.global [%0], [%1], 16;\n" :: "r"(saddr), "l"(g));
}
__device__ __forceinline__ void cp_commit() {
    asm volatile("cp.async.commit_group;\n" ::: "memory");
}
__device__ __forceinline__ void cp_wait2() {
    asm volatile("cp.async.wait_group 2;\n" ::: "memory");
}
__device__ __forceinline__ void ldsm_x4(uint32_t* r, uint32_t addr) {
    asm volatile("ldmatrix.sync.aligned.m8n8.x4.shared.b16 {%0,%1,%2,%3}, [%4];"
                 : "=r"(r[0]), "=r"(r[1]), "=r"(r[2]), "=r"(r[3]) : "r"(addr));
}
__device__ __forceinline__ void ldsm_x4_t(uint32_t* r, uint32_t addr) {
    asm volatile("ldmatrix.sync.aligned.m8n8.x4.trans.shared.b16 {%0,%1,%2,%3}, [%4];"
                 : "=r"(r[0]), "=r"(r[1]), "=r"(r[2]), "=r"(r[3]) : "r"(addr));
}
__device__ __forceinline__ void mma_f16(float* d, const uint32_t* a, uint32_t b0, uint32_t b1) {
    asm volatile(
        "mma.sync.aligned.m16n8k16.row.col.f32.f16.f16.f32 "
        "{%0,%1,%2,%3}, {%4,%5,%6,%7}, {%8,%9}, {%0,%1,%2,%3};\n"
        : "+f"(d[0]), "+f"(d[1]), "+f"(d[2]), "+f"(d[3])
        : "r"(a[0]), "r"(a[1]), "r"(a[2]), "r"(a[3]), "r"(b0), "r"(b1));
}

// =================== Kernel 0: fp32 -> fp16 conversion ========================
__global__ __launch_bounds__(256) void convert_kernel(
    const float* __restrict__ src, __half* __restrict__ dst, size_t n4)
{
    size_t i = (size_t)blockIdx.x * blockDim.x + threadIdx.x;
    size_t stride = (size_t)gridDim.x * blockDim.x;
    const float4* s4 = reinterpret_cast<const float4*>(src);
    uint2* d2 = reinterpret_cast<uint2*>(dst);
    for (; i < n4; i += stride) {
        float4 v = s4[i];
        __half2 lo = __floats2half2_rn(v.x, v.y);
        __half2 hi = __floats2half2_rn(v.z, v.w);
        uint2 o;
        o.x = *reinterpret_cast<uint32_t*>(&lo);
        o.y = *reinterpret_cast<uint32_t*>(&hi);
        d2[i] = o;
    }
}

// ============== Kernel 1: Z = X @ W_xh via mma.sync fp16 ======================
// BM=128, BN=128, BK=32 halves. 8 warps 2(m)x4(n), warp tile 64x32.
// 4-stage cp.async pipeline, 2 CTAs/SM.
#define BM 128
#define BN 128
#define BK 32
#define STAGES 4
#define NITER (VOCAB / BK)           // 1000

#define A_PAD 40                     // halves per A row (80B: 5 granules mod 8 -> distinct)
#define B_PAD 136                    // halves per B row (272B: 1 granule mod 8 -> distinct)
#define A_HALVES (BM * A_PAD)        // 5120 (10.24 KB)
#define B_HALVES (BK * B_PAD)        // 4352 (8.70 KB)
#define STAGE_HALVES (A_HALVES + B_HALVES)
#define GEMM_DYNSMEM (STAGES * STAGE_HALVES * 2)   // ~75.8 KB

extern __shared__ __half hsmem[];

__global__ __launch_bounds__(256, 2) void gemm_tc_kernel(float* __restrict__ C)
{
    const __half* A = g_Xh;        // [6400, 32000] K-contig
    const __half* B = g_Wh;        // [32000, 1024] N-contig
    const int tid  = threadIdx.x;
    const int wid  = tid >> 5;
    const int lane = tid & 31;
    const int wm   = wid >> 2;      // 0..1
    const int wn   = wid & 3;       // 0..3
    const int m0   = blockIdx.y * BM;
    const int n0   = blockIdx.x * BN;

    const uint32_t sbase = smem_u32(hsmem);

    auto load_stage = [&](int it) {
        const int s = it & 3;
        const uint32_t abase = sbase + s * STAGE_HALVES * 2;
        const uint32_t bbase = abase + A_HALVES * 2;
        const __half* Ag = A + (size_t)m0 * VOCAB + (size_t)it * BK;
        const __half* Bg = B + (size_t)it * BK * HID + n0;
#pragma unroll
        for (int i = 0; i < 2; i++) {     // A: 512 granules (128 rows x 4)
            int q = tid + i * 256;
            int r = q >> 2, c = q & 3;
            cp_async16(abase + (r * A_PAD + c * 8) * 2,
                       Ag + (size_t)r * VOCAB + c * 8);
        }
#pragma unroll
        for (int i = 0; i < 2; i++) {     // B: 512 granules (32 rows x 16)
            int q = tid + i * 256;
            int r = q >> 4, c = q & 15;
            cp_async16(bbase + (r * B_PAD + c * 8) * 2,
                       Bg + (size_t)r * HID + c * 8);
        }
        cp_commit();
    };

    // ldmatrix per-thread source rows (lane q: tile=q/8, i=q%8)
    const int lt = lane >> 3, li = lane & 7;
    // A tiles: (m0-7,k0-7),(m8-15,k0-7),(m0-7,k8-15),(m8-15,k8-15)
    const int a_row_off = wm * 64 + (lt & 1) * 8 + li;       // + mt*16
    const int a_col_off = (lt >> 1) * 8;                     // + k16*16
    // B tiles (trans): (k0-7,n0),(k8-15,n0),(k0-7,n0+8),(k8-15,n0+8)
    const int b_row_off = (lt & 1) * 8 + li;                 // + k16*16
    const int b_col_off = wn * 32 + (lt >> 1) * 8;           // + p*16

    float acc[4][4][4];
#pragma unroll
    for (int i = 0; i < 4; i++)
#pragma unroll
        for (int j = 0; j < 4; j++)
#pragma unroll
            for (int k = 0; k < 4; k++) acc[i][j][k] = 0.0f;

    load_stage(0); load_stage(1); load_stage(2);

#pragma unroll 1
    for (int it = 0; it < NITER; it++) {
        cp_wait2();
        __syncthreads();
        const int s = it & 3;
        const uint32_t As = sbase + s * STAGE_HALVES * 2;
        const uint32_t Bs = As + A_HALVES * 2;

#pragma unroll
        for (int k16 = 0; k16 < BK / 16; k16++) {
            uint32_t af[4][4];
#pragma unroll
            for (int mt = 0; mt < 4; mt++)
                ldsm_x4(af[mt], As + ((a_row_off + mt * 16) * A_PAD +
                                      a_col_off + k16 * 16) * 2);
            uint32_t bf[2][4];
#pragma unroll
            for (int p = 0; p < 2; p++)
                ldsm_x4_t(bf[p], Bs + ((b_row_off + k16 * 16) * B_PAD +
                                       b_col_off + p * 16) * 2);
#pragma unroll
            for (int mt = 0; mt < 4; mt++)
#pragma unroll
                for (int nt = 0; nt < 4; nt++)
                    mma_f16(acc[mt][nt], af[mt],
                            bf[nt >> 1][(nt & 1) * 2], bf[nt >> 1][(nt & 1) * 2 + 1]);
        }

        if (it + 3 < NITER) load_stage(it + 3);
    }

    // epilogue: direct register -> global stores (float2)
    const int g = lane >> 2, t = lane & 3;
#pragma unroll
    for (int mt = 0; mt < 4; mt++) {
#pragma unroll
        for (int nt = 0; nt < 4; nt++) {
            const int r0 = m0 + wm * 64 + mt * 16 + g;
            const int c  = n0 + wn * 32 + nt * 8 + 2 * t;
            float2 v0 = make_float2(acc[mt][nt][0], acc[mt][nt][1]);
            float2 v1 = make_float2(acc[mt][nt][2], acc[mt][nt][3]);
            *reinterpret_cast<float2*>(C + (size_t)r0 * HID + c) = v0;
            *reinterpret_cast<float2*>(C + (size_t)(r0 + 8) * HID + c) = v1;
        }
    }
}

// ============ profiler-alignment dummy ========================================
__global__ void dummy_kernel() {}

// ================= Kernel 2: recurrence + pool + fc + softmax =================
#define NB 128
#define CPB 8

__device__ __forceinline__ void gridbar() {
    __syncthreads();
    if (threadIdx.x == 0) {
        unsigned gen = g_bar_gen;
        __threadfence();
        if (atomicAdd(&g_bar_cnt, 1) == NB - 1) {
            atomicExch(&g_bar_cnt, 0);
            __threadfence();
            g_bar_gen = gen + 1;
        } else {
            while (g_bar_gen == gen) { __nanosleep(64); }
            __threadfence();
        }
    }
    __syncthreads();
}

__global__ __launch_bounds__(256, 1) void rnn_recurrence_kernel(
    const float* __restrict__ W_hh,
    const float* __restrict__ b_h,
    const float* __restrict__ fc_w,
    const float* __restrict__ fc_b,
    float* __restrict__ out)
{
    __shared__ float Ws[CPB][HID];
    const int tid = threadIdx.x;
    const int wid = tid >> 5;
    const int lane = tid & 31;
    const int c0 = blockIdx.x * CPB;

    for (int i = tid; i < CPB * HID; i += 256) {
        int c = i >> 10, k = i & (HID - 1);
        Ws[c][k] = W_hh[k * HID + c0 + c];
    }
    for (int i = tid; i < 200; i += 256)
        g_h[0][blockIdx.x * 200 + i] = 0.0f;
    gridbar();

    const float4* Ws4 = reinterpret_cast<const float4*>(&Ws[0][0]);

    for (int t = 0; t < T_STEPS; t++) {
        const int rb = t & 1, wb = rb ^ 1;
        const float4* h4 = reinterpret_cast<const float4*>(g_h[rb]);
        for (int b = wid; b < BATCH; b += 8) {
            float acc[CPB];
#pragma unroll
            for (int c = 0; c < CPB; c++) acc[c] = 0.0f;
            const float4* hrow = h4 + b * (HID / 4);
#pragma unroll
            for (int p = 0; p < 8; p++) {
                float4 hv = __ldcg(&hrow[p * 32 + lane]);
#pragma unroll
                for (int c = 0; c < CPB; c++) {
                    float4 wv = Ws4[c * 256 + p * 32 + lane];
                    acc[c] += hv.x * wv.x + hv.y * wv.y + hv.z * wv.z + hv.w * wv.w;
                }
            }
#pragma unroll
            for (int c = 0; c < CPB; c++) {
#pragma unroll
                for (int off = 16; off; off >>= 1)
                    acc[c] += __shfl_xor_sync(0xFFFFFFFFu, acc[c], off);
            }
            if (lane == 0) {
                const float* zrow = g_Z + ((size_t)t * BATCH + b) * HID + c0;
                float* hn = g_h[wb] + b * HID + c0;
#pragma unroll
                for (int c = 0; c < CPB; c++)
                    hn[c] = tanhf(zrow[c] + b_h[c0 + c] + acc[c]);
            }
        }
        gridbar();
    }

    if (blockIdx.x == 0) {
        __shared__ float red0[8], red1[8];
        float l0 = 0.0f, l1 = 0.0f;
        for (int n = tid; n < HID; n += 256) {
            float s = 0.0f;
#pragma unroll
            for (int b = 0; b < BATCH; b++)
                s += __ldcg(&g_h[0][b * HID + n]);
            float pooled = s * (1.0f / BATCH);
            l0 += pooled * fc_w[n * CLS + 0];
            l1 += pooled * fc_w[n * CLS + 1];
        }
#pragma unroll
        for (int off = 16; off; off >>= 1) {
            l0 += __shfl_xor_sync(0xFFFFFFFFu, l0, off);
            l1 += __shfl_xor_sync(0xFFFFFFFFu, l1, off);
        }
        if (lane == 0) { red0[wid] = l0; red1[wid] = l1; }
        __syncthreads();
        if (tid == 0) {
            float a = 0.0f, c = 0.0f;
#pragma unroll
            for (int w = 0; w < 8; w++) { a += red0[w]; c += red1[w]; }
            a += fc_b[0]; c += fc_b[1];
            float mx = fmaxf(a, c);
            float e0 = expf(a - mx), e1 = expf(c - mx);
            float inv = 1.0f / (e0 + e1);
            out[0] = e0 * inv;
            out[1] = e1 * inv;
        }
    }
}

// ================================ launcher ====================================
extern "C" void kernel_launch(void* const* d_in, const int* in_sizes, int n_in,
                              void* d_out, int out_size) {
    const float* X    = (const float*)d_in[0];
    const float* W_xh = (const float*)d_in[1];
    const float* W_hh = (const float*)d_in[2];
    const float* b_h  = (const float*)d_in[3];
    const float* fc_w = (const float*)d_in[4];
    const float* fc_b = (const float*)d_in[5];
    float* out = (float*)d_out;

    float* Z;
    cudaGetSymbolAddress((void**)&Z, g_Z);
    __half* Xh;
    cudaGetSymbolAddress((void**)&Xh, g_Xh);
    __half* Wh;
    cudaGetSymbolAddress((void**)&Wh, g_Wh);

    cudaFuncSetAttribute(gemm_tc_kernel,
                         cudaFuncAttributeMaxDynamicSharedMemorySize, GEMM_DYNSMEM);

    // 7 launches/replay: with ncu -s 5 -c 1, launch #6 = GEMM gets profiled.
    convert_kernel<<<2048, 256>>>(X, Xh, (size_t)M_GEMM * VOCAB / 4);      // #1
    convert_kernel<<<1024, 256>>>(W_xh, Wh, (size_t)VOCAB * HID / 4);      // #2
    dummy_kernel<<<1, 32>>>();                                             // #3
    dummy_kernel<<<1, 32>>>();                                             // #4
    dummy_kernel<<<1, 32>>>();                                             // #5
    dim3 ggrid(HID / BN, M_GEMM / BM);         // (8, 50)
    gemm_tc_kernel<<<ggrid, 256, GEMM_DYNSMEM>>>(Z);                       // #6
    rnn_recurrence_kernel<<<NB, 256>>>(W_hh, b_h, fc_w, fc_b, out);        // #7
}